// round 12
// baseline (speedup 1.0000x reference)
#include <cuda_runtime.h>
#include <cuda_bf16.h>
#include <math.h>
#include <stdint.h>

// ---------------- problem constants ----------------
#define CN0 100000
#define CN1 20000
#define CN2 4000
#define CR 3
#define CE0 160000
#define CE1 64000
#define CHID 128
#define CFEAT 256

// weight buffer offsets (elements) — natural [K,128] layout, bf16 split
#define OFF_EMBED 0
#define OFF_ATTN  16384
#define OFF_L1FC1 32768
#define OFF_L1FC2 131072
#define OFF_L1FC3 425984
#define OFF_L2FC1 524288
#define OFF_L2FC2 622592
#define OFF_L2FC3 917504
#define WT_TOTAL  1015808

// ---------------- device scratch ----------------
__device__ __align__(16) float g_z[CR * CN1 * CHID];
__device__ __align__(16) __nv_bfloat16 g_xh[CN0 * 128];
__device__ __align__(16) __nv_bfloat16 g_xl[CN0 * 128];
__device__ __align__(16) __nv_bfloat16 g_f0h[CN0 * CFEAT];
__device__ __align__(16) __nv_bfloat16 g_f0l[CN0 * CFEAT];
__device__ __align__(16) __nv_bfloat16 g_f1h[CN1 * CFEAT];
__device__ __align__(16) __nv_bfloat16 g_f1l[CN1 * CFEAT];
__device__ __align__(16) __nv_bfloat16 g_msgh[CR * CN1 * 768];
__device__ __align__(16) __nv_bfloat16 g_msgl[CR * CN1 * 768];
__device__ __align__(16) __nv_bfloat16 g_Hh[CR * CN1 * 256];
__device__ __align__(16) __nv_bfloat16 g_Hl[CR * CN1 * 256];
__device__ __align__(16) __nv_bfloat16 g_wth[WT_TOTAL];
__device__ __align__(16) __nv_bfloat16 g_wtl[WT_TOTAL];
__device__ int   g_cnt[CR * CN1];           // INVARIANT: zero at entry (layer1)
__device__ int   g_rowptr[CR * (CN1 + 1)];
__device__ int   g_cursor[CR * (CN1 + 1)];
__device__ int   g_sorted[CR * CE0];
__device__ int   g_cnt2[CR * CN2];          // INVARIANT: zero at entry (layer2)
__device__ int   g_rowptr2[CR * (CN2 + 1)];
__device__ int   g_cursor2[CR * (CN2 + 1)];
__device__ int   g_sorted2[CR * CE1];
__device__ float g_s[CR];                   // INVARIANT: zero at entry
__device__ float g_beta[CR];

// ---------------- helpers ----------------
__device__ __forceinline__ uint32_t smem_u32(const void* p) {
    uint32_t a;
    asm("{ .reg .u64 t; cvta.to.shared.u64 t, %1; cvt.u32.u64 %0, t; }" : "=r"(a) : "l"(p));
    return a;
}
__device__ __forceinline__ void bsplit(float v, __nv_bfloat16& h, __nv_bfloat16& l) {
    h = __float2bfloat16(v);
    l = __float2bfloat16(v - __bfloat162float(h));
}
__device__ __forceinline__ uint32_t pack2(__nv_bfloat16 a, __nv_bfloat16 b) {
    __nv_bfloat162 p; p.x = a; p.y = b;
    return *(uint32_t*)&p;
}
__device__ __forceinline__ uint2 split4(float4 v, uint2& lo) {
    __nv_bfloat16 h0, l0, h1, l1, h2, l2, h3, l3;
    bsplit(v.x, h0, l0); bsplit(v.y, h1, l1);
    bsplit(v.z, h2, l2); bsplit(v.w, h3, l3);
    lo = make_uint2(pack2(l0, l1), pack2(l2, l3));
    return make_uint2(pack2(h0, h1), pack2(h2, h3));
}
__device__ __forceinline__ void cp16(uint32_t dst, const void* src, int valid) {
    asm volatile("cp.async.cg.shared.global [%0], [%1], 16, %2;"
                 :: "r"(dst), "l"(src), "r"(valid ? 16 : 0) : "memory");
}
template <int N> __device__ __forceinline__ void cpwait() {
    asm volatile("cp.async.wait_group %0;" :: "n"(N) : "memory");
}
__device__ __forceinline__ void cpcommit() {
    asm volatile("cp.async.commit_group;" ::: "memory");
}
__device__ __forceinline__ void mma16816(float* c, const uint32_t* a, uint32_t b0, uint32_t b1) {
    asm volatile("mma.sync.aligned.m16n8k16.row.col.f32.bf16.bf16.f32 "
        "{%0,%1,%2,%3}, {%4,%5,%6,%7}, {%8,%9}, {%0,%1,%2,%3};"
        : "+f"(c[0]), "+f"(c[1]), "+f"(c[2]), "+f"(c[3])
        : "r"(a[0]), "r"(a[1]), "r"(a[2]), "r"(a[3]), "r"(b0), "r"(b1));
}
__device__ __forceinline__ void ldmx4(uint32_t* r, uint32_t addr) {
    asm volatile("ldmatrix.sync.aligned.m8n8.x4.shared.b16 {%0,%1,%2,%3}, [%4];"
        : "=r"(r[0]), "=r"(r[1]), "=r"(r[2]), "=r"(r[3]) : "r"(addr));
}
__device__ __forceinline__ void ldmx4t(uint32_t* r, uint32_t addr) {
    asm volatile("ldmatrix.sync.aligned.m8n8.x4.trans.shared.b16 {%0,%1,%2,%3}, [%4];"
        : "=r"(r[0]), "=r"(r[1]), "=r"(r[2]), "=r"(r[3]) : "r"(addr));
}

// ---------------- tensor-core GEMM (mma.sync + ldmatrix, bf16 3-term split) ----------------
#define KC 32
#define SROW 40
#define BROWB 272
#define A_L_OFF 10240
#define B_H_OFF 20480
#define B_L_OFF 29184
#define STAGE_BYTES 37888
#define GEMM_SMEM_BYTES (2 * STAGE_BYTES)   // 75776
#define ZT_BYTES 10240
#define W1_OFF 40960

__global__ void __launch_bounds__(256, 2)
gemm_tc(const __nv_bfloat16* __restrict__ Ah, const __nv_bfloat16* __restrict__ Al,
        const __nv_bfloat16* __restrict__ Bh_g, const __nv_bfloat16* __restrict__ Bl_g,
        const float* __restrict__ bias,
        float* __restrict__ Cf, __nv_bfloat16* __restrict__ Ch, __nv_bfloat16* __restrict__ Cl,
        int ldc, int M, int K, int relu,
        long aS, long bS, long biasS, long cS,
        int Msplit, int attn_fuse,
        const __nv_bfloat16* __restrict__ w1h, const float* __restrict__ b1a,
        const float* __restrict__ w2, float* __restrict__ s_out,
        int dual,
        const __nv_bfloat16* Ah2, const __nv_bfloat16* Al2,
        const __nv_bfloat16* Bh2, const __nv_bfloat16* Bl2,
        const float* bias2, __nv_bfloat16* Ch2, __nv_bfloat16* Cl2,
        int K2, long aS2) {
    extern __shared__ __align__(16) char sm[];
    __shared__ float bias_s[128];
    __shared__ float b1_s[128];
    __shared__ float w2_s[128];
    __shared__ float red_s[8];
    uint32_t sb = smem_u32(sm);
    int t = threadIdx.x;
    int lane = t & 31, wid = t >> 5;
    int m0 = blockIdx.x * 128;
    int rrel = blockIdx.y;
    if (dual && rrel >= CR) {
        rrel -= CR;
        Ah = Ah2; Al = Al2; Bh_g = Bh2; Bl_g = Bl2; bias = bias2;
        Ch = Ch2; Cl = Cl2; K = K2; aS = aS2;
        Bh_g += (size_t)rrel * (256L * 128); Bl_g += (size_t)rrel * (256L * 128);
        bias += (size_t)rrel * 128;
        Ch += (size_t)rrel * cS; Cl += (size_t)rrel * cS;
        Ah += (size_t)rrel * aS; Al += (size_t)rrel * aS;
    } else {
        Ah += (size_t)rrel * aS;  Al += (size_t)rrel * aS;
        Bh_g += (size_t)rrel * bS; Bl_g += (size_t)rrel * bS;
        bias += (size_t)rrel * biasS;
        if (Cf) Cf += (size_t)rrel * cS;
        if (Ch) { Ch += (size_t)rrel * cS; Cl += (size_t)rrel * cS; }
    }
    if (t < 128) {
        bias_s[t] = bias[t];
        if (attn_fuse) { b1_s[t] = b1a[t]; w2_s[t] = w2[t]; }
    }

    float acc[2][8][4];
#pragma unroll
    for (int i = 0; i < 2; i++)
#pragma unroll
        for (int j = 0; j < 8; j++)
#pragma unroll
            for (int q = 0; q < 4; q++) acc[i][j][q] = 0.f;

    const int nC = K >> 5;
    const int wm = (wid >> 1) * 32, wn = (wid & 1) * 64;
    const int t4 = lane >> 2, q2 = (lane & 3) * 2;
    const int g = lane >> 3, lr = lane & 7;

    auto load_stage = [&](int st, int c) {
        uint32_t base = sb + st * STAGE_BYTES;
        int kb = c * KC;
#pragma unroll
        for (int h = 0; h < 2; h++) {
            int idx = t + h * 256;
            int arow = idx >> 2, aseg = idx & 3;
            uint32_t aoff = (uint32_t)(arow * (SROW * 2) + aseg * 16);
            int av = (m0 + arow) < M;
            size_t asrc = (size_t)(av ? (m0 + arow) : 0) * K + kb + aseg * 8;
            cp16(base + aoff,           Ah + asrc, av);
            cp16(base + A_L_OFF + aoff, Al + asrc, av);
            int brow = idx >> 4, bseg = idx & 15;
            uint32_t boff = (uint32_t)(brow * BROWB + bseg * 16);
            size_t bsrc = (size_t)(kb + brow) * 128 + bseg * 8;
            cp16(base + B_H_OFF + boff, Bh_g + bsrc, 1);
            cp16(base + B_L_OFF + boff, Bl_g + bsrc, 1);
        }
        cpcommit();
    };

    auto compute_stage = [&](int st) {
        uint32_t base = sb + st * STAGE_BYTES;
#pragma unroll
        for (int k16 = 0; k16 < 2; k16++) {
            int k0 = k16 * 16;
            int arow = wm + (g & 1) * 8 + lr;
            int acol = k0 + (g >> 1) * 8;
            uint32_t ah[2][4], al[2][4];
#pragma unroll
            for (int i = 0; i < 2; i++) {
                uint32_t aoff = (uint32_t)(((arow + i * 16) * SROW + acol) * 2);
                ldmx4(ah[i], base + aoff);
                ldmx4(al[i], base + A_L_OFF + aoff);
            }
#pragma unroll
            for (int jp = 0; jp < 4; jp++) {
                int n0 = wn + jp * 16;
                uint32_t boff = (uint32_t)((k0 + (g & 1) * 8 + lr) * BROWB
                                           + (n0 + (g >> 1) * 8) * 2);
                uint32_t bh[4], bl[4];
                ldmx4t(bh, base + B_H_OFF + boff);
                ldmx4t(bl, base + B_L_OFF + boff);
#pragma unroll
                for (int jj = 0; jj < 2; jj++) {
                    int j = jp * 2 + jj;
#pragma unroll
                    for (int i = 0; i < 2; i++) {
                        mma16816(acc[i][j], ah[i], bh[jj * 2], bh[jj * 2 + 1]);
                        mma16816(acc[i][j], ah[i], bl[jj * 2], bl[jj * 2 + 1]);
                        mma16816(acc[i][j], al[i], bh[jj * 2], bh[jj * 2 + 1]);
                    }
                }
            }
        }
    };

    load_stage(0, 0);
    for (int c = 0; c < nC; c++) {
        if (c + 1 < nC) {
            load_stage((c + 1) & 1, c + 1);
            cpwait<1>();
        } else {
            cpwait<0>();
        }
        __syncthreads();
        compute_stage(c & 1);
        __syncthreads();
    }

    if (attn_fuse) {
#pragma unroll
        for (int i = 0; i < 2; i++) {
            int rl = wm + i * 16 + t4;
            int r0 = m0 + rl;
#pragma unroll
            for (int j = 0; j < 8; j++) {
                int col = wn + j * 8 + q2;
                float v00 = acc[i][j][0] + bias_s[col];
                float v01 = acc[i][j][1] + bias_s[col + 1];
                float v10 = acc[i][j][2] + bias_s[col];
                float v11 = acc[i][j][3] + bias_s[col + 1];
                if (r0 < M) *(float2*)(Cf + (size_t)r0 * ldc + col) = make_float2(v00, v01);
                if (r0 + 8 < M) *(float2*)(Cf + (size_t)(r0 + 8) * ldc + col) = make_float2(v10, v11);
                uint32_t zoff = (uint32_t)(col >> 5) * ZT_BYTES;
                uint32_t cw = (uint32_t)(col & 31);
                *(uint32_t*)(sm + zoff + (rl * SROW + cw) * 2) =
                    pack2(__float2bfloat16(v00), __float2bfloat16(v01));
                *(uint32_t*)(sm + zoff + ((rl + 8) * SROW + cw) * 2) =
                    pack2(__float2bfloat16(v10), __float2bfloat16(v11));
            }
        }
        __syncthreads();
        float tacc[2][8][4];
#pragma unroll
        for (int i = 0; i < 2; i++)
#pragma unroll
            for (int j = 0; j < 8; j++)
#pragma unroll
                for (int q = 0; q < 4; q++) tacc[i][j][q] = 0.f;
        for (int c = 0; c < 4; c++) {
#pragma unroll
            for (int h = 0; h < 2; h++) {
                int idx = t + h * 256;
                int brow = idx >> 4, bseg = idx & 15;
                cp16(sb + W1_OFF + (uint32_t)(brow * BROWB + bseg * 16),
                     w1h + (size_t)(c * 32 + brow) * 128 + bseg * 8, 1);
            }
            cpcommit();
            cpwait<0>();
            __syncthreads();
            uint32_t zb = sb + (uint32_t)c * ZT_BYTES;
#pragma unroll
            for (int k16 = 0; k16 < 2; k16++) {
                int k0 = k16 * 16;
                int arow = wm + (g & 1) * 8 + lr;
                int acol = k0 + (g >> 1) * 8;
                uint32_t ah[2][4];
#pragma unroll
                for (int i = 0; i < 2; i++)
                    ldmx4(ah[i], zb + (uint32_t)(((arow + i * 16) * SROW + acol) * 2));
#pragma unroll
                for (int jp = 0; jp < 4; jp++) {
                    int n0 = wn + jp * 16;
                    uint32_t bh[4];
                    ldmx4t(bh, sb + W1_OFF +
                           (uint32_t)((k0 + (g & 1) * 8 + lr) * BROWB + (n0 + (g >> 1) * 8) * 2));
#pragma unroll
                    for (int jj = 0; jj < 2; jj++)
#pragma unroll
                        for (int i = 0; i < 2; i++)
                            mma16816(tacc[i][jp * 2 + jj], ah[i], bh[jj * 2], bh[jj * 2 + 1]);
                }
            }
            __syncthreads();
        }
        float part = 0.f;
#pragma unroll
        for (int i = 0; i < 2; i++) {
            int r0 = m0 + wm + i * 16 + t4;
#pragma unroll
            for (int j = 0; j < 8; j++) {
                int col = wn + j * 8 + q2;
                float b0v = b1_s[col], b1v = b1_s[col + 1];
                float w0v = w2_s[col], w1v = w2_s[col + 1];
                if (r0 < M) {
                    part += tanhf(tacc[i][j][0] + b0v) * w0v;
                    part += tanhf(tacc[i][j][1] + b1v) * w1v;
                }
                if (r0 + 8 < M) {
                    part += tanhf(tacc[i][j][2] + b0v) * w0v;
                    part += tanhf(tacc[i][j][3] + b1v) * w1v;
                }
            }
        }
        for (int o = 16; o; o >>= 1) part += __shfl_xor_sync(0xffffffffu, part, o);
        if (lane == 0) red_s[wid] = part;
        __syncthreads();
        if (t == 0) {
            float tot = 0.f;
#pragma unroll
            for (int i = 0; i < 8; i++) tot += red_s[i];
            atomicAdd(s_out + rrel, tot);
        }
        return;
    }

#pragma unroll
    for (int i = 0; i < 2; i++) {
        int r0 = m0 + wm + i * 16 + t4;
#pragma unroll
        for (int j = 0; j < 8; j++) {
            int col = wn + j * 8 + q2;
            float b0v = bias_s[col], b1v = bias_s[col + 1];
            float v00 = acc[i][j][0] + b0v, v01 = acc[i][j][1] + b1v;
            float v10 = acc[i][j][2] + b0v, v11 = acc[i][j][3] + b1v;
            if (relu) {
                v00 = fmaxf(v00, 0.f); v01 = fmaxf(v01, 0.f);
                v10 = fmaxf(v10, 0.f); v11 = fmaxf(v11, 0.f);
            }
            if (r0 < M) {
                if (Cf) *(float2*)(Cf + (size_t)r0 * ldc + col) = make_float2(v00, v01);
                if (Ch && r0 < Msplit) {
                    __nv_bfloat16 h0, l0, h1, l1;
                    bsplit(v00, h0, l0); bsplit(v01, h1, l1);
                    *(uint32_t*)(Ch + (size_t)r0 * ldc + col) = pack2(h0, h1);
                    *(uint32_t*)(Cl + (size_t)r0 * ldc + col) = pack2(l0, l1);
                }
            }
            if (r0 + 8 < M) {
                if (Cf) *(float2*)(Cf + (size_t)(r0 + 8) * ldc + col) = make_float2(v10, v11);
                if (Ch && r0 + 8 < Msplit) {
                    __nv_bfloat16 h0, l0, h1, l1;
                    bsplit(v10, h0, l0); bsplit(v11, h1, l1);
                    *(uint32_t*)(Ch + (size_t)(r0 + 8) * ldc + col) = pack2(h0, h1);
                    *(uint32_t*)(Cl + (size_t)(r0 + 8) * ldc + col) = pack2(l0, l1);
                }
            }
        }
    }
}

// ---------------- conversions (vectorized) ----------------
__global__ void split_k(const float* __restrict__ src, __nv_bfloat16* __restrict__ h,
                        __nv_bfloat16* __restrict__ l, long n4) {
    long i = (long)blockIdx.x * blockDim.x + threadIdx.x;
    if (i >= n4) return;
    float4 v = ((const float4*)src)[i];
    uint2 lo, hi = split4(v, lo);
    ((uint2*)h)[i] = hi;
    ((uint2*)l)[i] = lo;
}
__global__ void wsplit_k(const float* w0, const float* w1, const float* w2,
                         const float* w3, const float* w4, const float* w5,
                         const float* w6, const float* w7,
                         __nv_bfloat16* __restrict__ h, __nv_bfloat16* __restrict__ l) {
    long i4 = (long)blockIdx.x * blockDim.x + threadIdx.x;
    if (i4 >= WT_TOTAL / 4) return;
    long i = i4 * 4;
    const float* src; long base;
    if      (i < OFF_ATTN)  { src = w0; base = OFF_EMBED; }
    else if (i < OFF_L1FC1) { src = w1; base = OFF_ATTN; }
    else if (i < OFF_L1FC2) { src = w2; base = OFF_L1FC1; }
    else if (i < OFF_L1FC3) { src = w3; base = OFF_L1FC2; }
    else if (i < OFF_L2FC1) { src = w4; base = OFF_L1FC3; }
    else if (i < OFF_L2FC2) { src = w5; base = OFF_L2FC1; }
    else if (i < OFF_L2FC3) { src = w6; base = OFF_L2FC2; }
    else                    { src = w7; base = OFF_L2FC3; }
    float4 v = *(const float4*)(src + (i - base));
    uint2 lo, hi = split4(v, lo);
    *(uint2*)(h + i) = hi;
    *(uint2*)(l + i) = lo;
}

// ---------------- CSR build (batched over R) ----------------
__global__ void hist_k(const int* __restrict__ dst, int E, int n, int* cnt) {
    int e = blockIdx.x * blockDim.x + threadIdx.x;
    if (e < CR * E) {
        int r = e / E;
        atomicAdd(&cnt[r * n + dst[e]], 1);
    }
}
__global__ void scan_k(int* __restrict__ cnt_g, int* rowptr_g, int* cursor_g, int n) {
    int rel = blockIdx.x;
    int* cnt = cnt_g + rel * n;
    int* rowptr = rowptr_g + rel * (n + 1);
    int* cursor = cursor_g + rel * (n + 1);
    __shared__ int sh[1024];
    __shared__ int carry_s;
    if (threadIdx.x == 0) carry_s = 0;
    __syncthreads();
    for (int base = 0; base < n; base += 1024) {
        int i = base + threadIdx.x;
        int v = (i < n) ? cnt[i] : 0;
        sh[threadIdx.x] = v;
        __syncthreads();
        for (int off = 1; off < 1024; off <<= 1) {
            int add = (threadIdx.x >= off) ? sh[threadIdx.x - off] : 0;
            __syncthreads();
            sh[threadIdx.x] += add;
            __syncthreads();
        }
        int carry = carry_s;
        if (i < n) {
            int excl = carry + sh[threadIdx.x] - v;
            rowptr[i] = excl;
            cursor[i] = excl;
            cnt[i] = 0;
        }
        __syncthreads();
        if (threadIdx.x == 0) carry_s = carry + sh[1023];
        __syncthreads();
    }
    if (threadIdx.x == 0) rowptr[n] = carry_s;
}
__global__ void scatter_k(const int* __restrict__ src, const int* __restrict__ dst,
                          int E, int n, int* cursor, int* sorted) {
    int e = blockIdx.x * blockDim.x + threadIdx.x;
    if (e < CR * E) {
        int r = e / E;
        int p = atomicAdd(&cursor[r * (n + 1) + dst[e]], 1);
        sorted[r * E + p] = src[e];
    }
}

// ---------------- segment aggregation: 32 threads/node, 8 feats, 4-edge unroll ----------------
__device__ __forceinline__ void load8(const __nv_bfloat16* fh, const __nv_bfloat16* fl,
                                      size_t off, float* v) {
    uint4 h = *(const uint4*)(fh + off);
    uint4 l = *(const uint4*)(fl + off);
    const __nv_bfloat162* hp = (const __nv_bfloat162*)&h;
    const __nv_bfloat162* lp = (const __nv_bfloat162*)&l;
#pragma unroll
    for (int k = 0; k < 4; k++) {
        float2 hf = __bfloat1622float2(hp[k]);
        float2 lf = __bfloat1622float2(lp[k]);
        v[2 * k]     = hf.x + lf.x;
        v[2 * k + 1] = hf.y + lf.y;
    }
}
__global__ void __launch_bounds__(256)
aggregate_k(const __nv_bfloat16* __restrict__ fh, const __nv_bfloat16* __restrict__ fl,
            const int* __restrict__ rowptr_g, const int* __restrict__ sorted_g,
            __nv_bfloat16* __restrict__ mh_g, __nv_bfloat16* __restrict__ ml_g,
            int N, int E) {
    int rel = blockIdx.y;
    const int* rowptr = rowptr_g + rel * (N + 1);
    const int* sorted = sorted_g + rel * E;
    __nv_bfloat16* mh = mh_g + (size_t)rel * N * 768;
    __nv_bfloat16* ml = ml_g + (size_t)rel * N * 768;
    int n = blockIdx.x * 8 + (threadIdx.x >> 5);
    if (n >= N) return;
    int f8 = (threadIdx.x & 31) * 8;
    int start = rowptr[n], end = rowptr[n + 1];
    int deg = end - start;
    float sum[8], mx[8];
#pragma unroll
    for (int k = 0; k < 8; k++) { sum[k] = 0.f; mx[k] = -3.402823e38f; }
    int e = start;
    for (; e + 3 < end; e += 4) {
        int i0 = sorted[e], i1 = sorted[e + 1], i2 = sorted[e + 2], i3 = sorted[e + 3];
        float v0[8], v1[8], v2[8], v3[8];
        load8(fh, fl, (size_t)i0 * CFEAT + f8, v0);
        load8(fh, fl, (size_t)i1 * CFEAT + f8, v1);
        load8(fh, fl, (size_t)i2 * CFEAT + f8, v2);
        load8(fh, fl, (size_t)i3 * CFEAT + f8, v3);
#pragma unroll
        for (int k = 0; k < 8; k++) {
            sum[k] += (v0[k] + v1[k]) + (v2[k] + v3[k]);
            mx[k] = fmaxf(mx[k], fmaxf(fmaxf(v0[k], v1[k]), fmaxf(v2[k], v3[k])));
        }
    }
    for (; e < end; e++) {
        int i0 = sorted[e];
        float v0[8];
        load8(fh, fl, (size_t)i0 * CFEAT + f8, v0);
#pragma unroll
        for (int k = 0; k < 8; k++) {
            sum[k] += v0[k];
            mx[k] = fmaxf(mx[k], v0[k]);
        }
    }
    if (deg == 0)
#pragma unroll
        for (int k = 0; k < 8; k++) mx[k] = 0.f;
    float inv = 1.0f / (float)max(deg, 1);
    size_t o = (size_t)n * 768 + f8;
    uint2 lo0, lo1, hi0, hi1;
    hi0 = split4(*(float4*)(mx + 0), lo0); hi1 = split4(*(float4*)(mx + 4), lo1);
    *(uint4*)(mh + o) = make_uint4(hi0.x, hi0.y, hi1.x, hi1.y);
    *(uint4*)(ml + o) = make_uint4(lo0.x, lo0.y, lo1.x, lo1.y);
    float mean[8];
#pragma unroll
    for (int k = 0; k < 8; k++) mean[k] = sum[k] * inv;
    hi0 = split4(*(float4*)(mean + 0), lo0); hi1 = split4(*(float4*)(mean + 4), lo1);
    *(uint4*)(mh + o + 256) = make_uint4(hi0.x, hi0.y, hi1.x, hi1.y);
    *(uint4*)(ml + o + 256) = make_uint4(lo0.x, lo0.y, lo1.x, lo1.y);
    hi0 = split4(*(float4*)(sum + 0), lo0); hi1 = split4(*(float4*)(sum + 4), lo1);
    *(uint4*)(mh + o + 512) = make_uint4(hi0.x, hi0.y, hi1.x, hi1.y);
    *(uint4*)(ml + o + 512) = make_uint4(lo0.x, lo0.y, lo1.x, lo1.y);
}

// ---------------- feature assembly (bf16 split only) ----------------
__global__ void __launch_bounds__(256)
fill_embed_k(const float* __restrict__ tss, const float* __restrict__ rs,
             const int* __restrict__ nid,
             __nv_bfloat16* __restrict__ f0h, __nv_bfloat16* __restrict__ f0l) {
    int n = blockIdx.x * 8 + (threadIdx.x >> 5);
    int lane = threadIdx.x & 31;
    if (n >= CN0) return;
    int id = nid[n];
    float4 v = (lane < 16)
        ? *(const float4*)&tss[(size_t)id * 64 + lane * 4]
        : *(const float4*)&rs[(size_t)id * 64 + (lane - 16) * 4];
    size_t o = (size_t)n * CFEAT + 128 + lane * 4;
    uint2 lo, hi = split4(v, lo);
    *(uint2*)(f0h + o) = hi;
    *(uint2*)(f0l + o) = lo;
}
__global__ void __launch_bounds__(256)
combine1_k(const float* __restrict__ z, const float* __restrict__ beta,
           const float* __restrict__ tss, const float* __restrict__ rs,
           const int* __restrict__ nid,
           __nv_bfloat16* __restrict__ f1h, __nv_bfloat16* __restrict__ f1l,
           int N) {
    int n = blockIdx.x * 4 + (threadIdx.x >> 6);
    if (n >= N) return;
    int c4 = (threadIdx.x & 63) * 4;
    float4 v;
    if (c4 < 128) {
        float b0 = beta[0], b1 = beta[1], b2 = beta[2];
        float4 z0 = *(const float4*)&z[(size_t)n * 128 + c4];
        float4 z1 = *(const float4*)&z[((size_t)N + n) * 128 + c4];
        float4 z2 = *(const float4*)&z[(2 * (size_t)N + n) * 128 + c4];
        v.x = fmaxf(b0 * z0.x + b1 * z1.x + b2 * z2.x, 0.f);
        v.y = fmaxf(b0 * z0.y + b1 * z1.y + b2 * z2.y, 0.f);
        v.z = fmaxf(b0 * z0.z + b1 * z1.z + b2 * z2.z, 0.f);
        v.w = fmaxf(b0 * z0.w + b1 * z1.w + b2 * z2.w, 0.f);
    } else if (c4 < 192) {
        v = *(const float4*)&tss[(size_t)nid[n] * 64 + (c4 - 128)];
    } else {
        v = *(const float4*)&rs[(size_t)nid[n] * 64 + (c4 - 192)];
    }
    size_t o = (size_t)n * CFEAT + c4;
    uint2 lo, hi = split4(v, lo);
    *(uint2*)(f1h + o) = hi;
    *(uint2*)(f1l + o) = lo;
}

__global__ void beta_k(float* __restrict__ s, float* beta, float invN) {
    if (threadIdx.x == 0) {
        float w0 = s[0] * invN, w1 = s[1] * invN, w2 = s[2] * invN;
        s[0] = 0.f; s[1] = 0.f; s[2] = 0.f;
        float m = fmaxf(w0, fmaxf(w1, w2));
        float e0 = expf(w0 - m), e1 = expf(w1 - m), e2 = expf(w2 - m);
        float d = e0 + e1 + e2;
        beta[0] = e0 / d; beta[1] = e1 / d; beta[2] = e2 / d;
    }
}
__global__ void final_k(const float* __restrict__ z, const float* __restrict__ beta,
                        const float* __restrict__ pred_w, const float* __restrict__ pred_b,
                        float* __restrict__ out, int N) {
    int n = blockIdx.x * 8 + (threadIdx.x >> 5);
    int lane = threadIdx.x & 31;
    if (n >= N) return;
    float b0 = beta[0], b1 = beta[1], b2 = beta[2];
    int c4 = lane * 4;
    float4 z0 = *(const float4*)&z[(size_t)n * 128 + c4];
    float4 z1 = *(const float4*)&z[((size_t)N + n) * 128 + c4];
    float4 z2 = *(const float4*)&z[(2 * (size_t)N + n) * 128 + c4];
    float4 w = *(const float4*)&pred_w[c4];
    float acc = (b0 * z0.x + b1 * z1.x + b2 * z2.x) * w.x
              + (b0 * z0.y + b1 * z1.y + b2 * z2.y) * w.y
              + (b0 * z0.z + b1 * z1.z + b2 * z2.z) * w.z
              + (b0 * z0.w + b1 * z1.w + b2 * z2.w) * w.w;
    for (int o = 16; o; o >>= 1) acc += __shfl_xor_sync(0xffffffffu, acc, o);
    if (lane == 0) out[n] = 1.f / (1.f + expf(-(acc + pred_b[0])));
}

// ---------------- host orchestration ----------------
struct SideStreams {
    cudaStream_t sB, sC, sD;
    cudaEvent_t evRoot, evB, evC, evD;
    SideStreams() {
        cudaStreamCreateWithFlags(&sB, cudaStreamNonBlocking);
        cudaStreamCreateWithFlags(&sC, cudaStreamNonBlocking);
        cudaStreamCreateWithFlags(&sD, cudaStreamNonBlocking);
        cudaEventCreateWithFlags(&evRoot, cudaEventDisableTiming);
        cudaEventCreateWithFlags(&evB, cudaEventDisableTiming);
        cudaEventCreateWithFlags(&evC, cudaEventDisableTiming);
        cudaEventCreateWithFlags(&evD, cudaEventDisableTiming);
    }
};

static inline void launch_gemm(int R, const __nv_bfloat16* Ah, const __nv_bfloat16* Al,
                               const __nv_bfloat16* Bh, const __nv_bfloat16* Bl,
                               const float* bias, float* Cf, __nv_bfloat16* Ch,
                               __nv_bfloat16* Cl, int ldc, int M, int K, int relu,
                               long aS, long bS, long biasS, long cS,
                               int Msplit, int attn_fuse = 0,
                               const __nv_bfloat16* w1h = nullptr,
                               const float* b1a = nullptr,
                               const float* w2 = nullptr, float* s_out = nullptr,
                               int dual = 0,
                               const __nv_bfloat16* Ah2 = nullptr,
                               const __nv_bfloat16* Al2 = nullptr,
                               const __nv_bfloat16* Bh2 = nullptr,
                               const __nv_bfloat16* Bl2 = nullptr,
                               const float* bias2 = nullptr,
                               __nv_bfloat16* Ch2 = nullptr, __nv_bfloat16* Cl2 = nullptr,
                               int K2 = 0, long aS2 = 0) {
    dim3 grid((M + 127) / 128, dual ? 2 * R : R);
    gemm_tc<<<grid, 256, GEMM_SMEM_BYTES>>>(Ah, Al, Bh, Bl, bias, Cf, Ch, Cl,
                                            ldc, M, K, relu, aS, bS, biasS, cS,
                                            Msplit, attn_fuse, w1h, b1a, w2, s_out,
                                            dual, Ah2, Al2, Bh2, Bl2, bias2, Ch2, Cl2,
                                            K2, aS2);
}

extern "C" void kernel_launch(void* const* d_in, const int* in_sizes, int n_in,
                              void* d_out, int out_size) {
    const float* x_user   = (const float*)d_in[0];
    const float* tss      = (const float*)d_in[1];
    const float* rs       = (const float*)d_in[2];
    const int*   src_nid0 = (const int*)d_in[3];
    const int*   src_nid1 = (const int*)d_in[4];
    const int*   e0_src   = (const int*)d_in[5];
    const int*   e0_dst   = (const int*)d_in[6];
    const int*   e1_src   = (const int*)d_in[7];
    const int*   e1_dst   = (const int*)d_in[8];
    const float* embed_w  = (const float*)d_in[9];
    const float* embed_b  = (const float*)d_in[10];
    const float* l1_fc1_w = (const float*)d_in[11];
    const float* l1_fc1_b = (const float*)d_in[12];
    const float* l1_fc2_w = (const float*)d_in[13];
    const float* l1_fc2_b = (const float*)d_in[14];
    const float* l1_fc3_w = (const float*)d_in[15];
    const float* l1_fc3_b = (const float*)d_in[16];
    const float* l2_fc1_w = (const float*)d_in[17];
    const float* l2_fc1_b = (const float*)d_in[18];
    const float* l2_fc2_w = (const float*)d_in[19];
    const float* l2_fc2_b = (const float*)d_in[20];
    const float* l2_fc3_w = (const float*)d_in[21];
    const float* l2_fc3_b = (const float*)d_in[22];
    const float* attn_w1  = (const float*)d_in[23];
    const float* attn_b1  = (const float*)d_in[24];
    const float* attn_w2  = (const float*)d_in[25];
    const float* pred_w   = (const float*)d_in[26];
    const float* pred_b   = (const float*)d_in[27];
    float* out = (float*)d_out;

    static SideStreams SS;   // created on first (uncaptured) call
    cudaFuncSetAttribute(gemm_tc, cudaFuncAttributeMaxDynamicSharedMemorySize, GEMM_SMEM_BYTES);

    float *z, *s, *beta;
    __nv_bfloat16 *xh, *xl, *f0h, *f0l, *f1h, *f1l, *msgh, *msgl, *Hh, *Hl, *wth, *wtl;
    int *cnt, *rowptr, *cursor, *sorted;
    int *cnt2, *rowptr2, *cursor2, *sorted2;
    cudaGetSymbolAddress((void**)&z, g_z);
    cudaGetSymbolAddress((void**)&s, g_s);
    cudaGetSymbolAddress((void**)&beta, g_beta);
    cudaGetSymbolAddress((void**)&xh, g_xh);
    cudaGetSymbolAddress((void**)&xl, g_xl);
    cudaGetSymbolAddress((void**)&f0h, g_f0h);
    cudaGetSymbolAddress((void**)&f0l, g_f0l);
    cudaGetSymbolAddress((void**)&f1h, g_f1h);
    cudaGetSymbolAddress((void**)&f1l, g_f1l);
    cudaGetSymbolAddress((void**)&msgh, g_msgh);
    cudaGetSymbolAddress((void**)&msgl, g_msgl);
    cudaGetSymbolAddress((void**)&Hh, g_Hh);
    cudaGetSymbolAddress((void**)&Hl, g_Hl);
    cudaGetSymbolAddress((void**)&wth, g_wth);
    cudaGetSymbolAddress((void**)&wtl, g_wtl);
    cudaGetSymbolAddress((void**)&cnt, g_cnt);
    cudaGetSymbolAddress((void**)&rowptr, g_rowptr);
    cudaGetSymbolAddress((void**)&cursor, g_cursor);
    cudaGetSymbolAddress((void**)&sorted, g_sorted);
    cudaGetSymbolAddress((void**)&cnt2, g_cnt2);
    cudaGetSymbolAddress((void**)&rowptr2, g_rowptr2);
    cudaGetSymbolAddress((void**)&cursor2, g_cursor2);
    cudaGetSymbolAddress((void**)&sorted2, g_sorted2);

    // ---- fork side streams ----
    cudaEventRecord(SS.evRoot, 0);
    cudaStreamWaitEvent(SS.sB, SS.evRoot, 0);
    cudaStreamWaitEvent(SS.sC, SS.evRoot, 0);
    cudaStreamWaitEvent(SS.sD, SS.evRoot, 0);

    // stream B: layer-1 CSR build
    hist_k<<<(CR * CE0 + 255) / 256, 256, 0, SS.sB>>>(e0_dst, CE0, CN1, cnt);
    scan_k<<<CR, 1024, 0, SS.sB>>>(cnt, rowptr, cursor, CN1);
    scatter_k<<<(CR * CE0 + 255) / 256, 256, 0, SS.sB>>>(e0_src, e0_dst, CE0, CN1, cursor, sorted);
    cudaEventRecord(SS.evB, SS.sB);

    // stream C: layer-2 CSR build (independent of everything else)
    hist_k<<<(CR * CE1 + 255) / 256, 256, 0, SS.sC>>>(e1_dst, CE1, CN2, cnt2);
    scan_k<<<CR, 1024, 0, SS.sC>>>(cnt2, rowptr2, cursor2, CN2);
    scatter_k<<<(CR * CE1 + 255) / 256, 256, 0, SS.sC>>>(e1_src, e1_dst, CE1, CN2, cursor2, sorted2);
    cudaEventRecord(SS.evC, SS.sC);

    // stream D: tss/rs gather into f0 cols 128..255
    fill_embed_k<<<(CN0 + 7) / 8, 256, 0, SS.sD>>>(tss, rs, src_nid0, f0h, f0l);
    cudaEventRecord(SS.evD, SS.sD);

    // main stream: conversions + embed GEMM (f0 cols 0..127)
    wsplit_k<<<(WT_TOTAL / 4 + 255) / 256, 256>>>(embed_w, attn_w1, l1_fc1_w, l1_fc2_w,
                                                  l1_fc3_w, l2_fc1_w, l2_fc2_w, l2_fc3_w,
                                                  wth, wtl);
    split_k<<<((long)CN0 * 32 + 255) / 256, 256>>>(x_user, xh, xl, (long)CN0 * 32);
    launch_gemm(1, xh, xl, wth + OFF_EMBED, wtl + OFF_EMBED, embed_b,
                nullptr, f0h, f0l, CFEAT, CN0, 128, 0, 0, 0, 0, 0, CN0);

    // join B and D (aggregate needs CSR1 + full f0)
    cudaStreamWaitEvent(0, SS.evB, 0);
    cudaStreamWaitEvent(0, SS.evD, 0);

    // ---- layer 1 ----
    aggregate_k<<<dim3((CN1 + 7) / 8, CR), 256>>>(f0h, f0l, rowptr, sorted, msgh, msgl, CN1, CE0);
    launch_gemm(CR, msgh, msgl, wth + OFF_L1FC2, wtl + OFF_L1FC2, l1_fc2_b,
                nullptr, Hh, Hl, 256, CN1, 768, 1,
                (long)CN1 * 768, 768L * 128, 128, (long)CN1 * 256, CN1,
                0, nullptr, nullptr, nullptr, nullptr,
                1, f0h, f0l, wth + OFF_L1FC1, wtl + OFF_L1FC1, l1_fc1_b,
                Hh + 128, Hl + 128, 256, 0);
    launch_gemm(CR, Hh, Hl, wth + OFF_L1FC3, wtl + OFF_L1FC3, l1_fc3_b,
                z, nullptr, nullptr, 128, CN1, 256, 0,
                (long)CN1 * 256, 256L * 128, 128, (long)CN1 * 128, 0,
                1, wth + OFF_ATTN, attn_b1, attn_w2, s);
    beta_k<<<1, 32>>>(s, beta, 1.0f / (float)CN1);
    combine1_k<<<(CN1 + 3) / 4, 256>>>(z, beta, tss, rs, src_nid1, f1h, f1l, CN1);

    // join C (layer-2 CSR done long ago)
    cudaStreamWaitEvent(0, SS.evC, 0);

    // ---- layer 2 ----
    aggregate_k<<<dim3((CN2 + 7) / 8, CR), 256>>>(f1h, f1l, rowptr2, sorted2, msgh, msgl, CN2, CE1);
    launch_gemm(CR, msgh, msgl, wth + OFF_L2FC2, wtl + OFF_L2FC2, l2_fc2_b,
                nullptr, Hh, Hl, 256, CN2, 768, 1,
                (long)CN2 * 768, 768L * 128, 128, (long)CN2 * 256, CN2,
                0, nullptr, nullptr, nullptr, nullptr,
                1, f1h, f1l, wth + OFF_L2FC1, wtl + OFF_L2FC1, l2_fc1_b,
                Hh + 128, Hl + 128, 256, 0);
    launch_gemm(CR, Hh, Hl, wth + OFF_L2FC3, wtl + OFF_L2FC3, l2_fc3_b,
                z, nullptr, nullptr, 128, CN2, 256, 0,
                (long)CN2 * 256, 256L * 128, 128, (long)CN2 * 128, 0,
                1, wth + OFF_ATTN, attn_b1, attn_w2, s);
    beta_k<<<1, 32>>>(s, beta, 1.0f / (float)CN2);
    final_k<<<(CN2 + 7) / 8, 256>>>(z, beta, pred_w, pred_b, out, CN2);
}

// round 13
// speedup vs baseline: 1.2874x; 1.2874x over previous
#include <cuda_runtime.h>
#include <cuda_bf16.h>
#include <math.h>
#include <stdint.h>

// ---------------- problem constants ----------------
#define CN0 100000
#define CN1 20000
#define CN2 4000
#define CR 3
#define CE0 160000
#define CE1 64000
#define CHID 128
#define CFEAT 256

// weight buffer offsets (elements) — natural [K,128] layout, bf16 split
#define OFF_EMBED 0
#define OFF_ATTN  16384
#define OFF_L1FC1 32768
#define OFF_L1FC2 131072
#define OFF_L1FC3 425984
#define OFF_L2FC1 524288
#define OFF_L2FC2 622592
#define OFF_L2FC3 917504
#define WT_TOTAL  1015808

// ---------------- device scratch ----------------
__device__ __align__(16) float g_z[CR * CN1 * CHID];
__device__ __align__(16) __nv_bfloat16 g_xh[CN0 * 128];
__device__ __align__(16) __nv_bfloat16 g_xl[CN0 * 128];
__device__ __align__(16) __nv_bfloat16 g_f0h[CN0 * CFEAT];
__device__ __align__(16) __nv_bfloat16 g_f0l[CN0 * CFEAT];
__device__ __align__(16) __nv_bfloat16 g_f1h[CN1 * CFEAT];
__device__ __align__(16) __nv_bfloat16 g_f1l[CN1 * CFEAT];
__device__ __align__(16) __nv_bfloat16 g_msgh[CR * CN1 * 768];
__device__ __align__(16) __nv_bfloat16 g_msgl[CR * CN1 * 768];
__device__ __align__(16) __nv_bfloat16 g_Hh[CR * CN1 * 256];
__device__ __align__(16) __nv_bfloat16 g_Hl[CR * CN1 * 256];
__device__ __align__(16) __nv_bfloat16 g_wth[WT_TOTAL];
__device__ __align__(16) __nv_bfloat16 g_wtl[WT_TOTAL];
__device__ int   g_cnt[CR * CN1];           // INVARIANT: zero at entry (layer1)
__device__ int   g_rowptr[CR * (CN1 + 1)];
__device__ int   g_cursor[CR * (CN1 + 1)];
__device__ int   g_sorted[CR * CE0];
__device__ int   g_cnt2[CR * CN2];          // INVARIANT: zero at entry (layer2)
__device__ int   g_rowptr2[CR * (CN2 + 1)];
__device__ int   g_cursor2[CR * (CN2 + 1)];
__device__ int   g_sorted2[CR * CE1];
__device__ float g_s[CR];                   // INVARIANT: zero at entry
__device__ float g_beta[CR];

// ---------------- helpers ----------------
__device__ __forceinline__ uint32_t smem_u32(const void* p) {
    uint32_t a;
    asm("{ .reg .u64 t; cvta.to.shared.u64 t, %1; cvt.u32.u64 %0, t; }" : "=r"(a) : "l"(p));
    return a;
}
__device__ __forceinline__ void bsplit(float v, __nv_bfloat16& h, __nv_bfloat16& l) {
    h = __float2bfloat16(v);
    l = __float2bfloat16(v - __bfloat162float(h));
}
__device__ __forceinline__ uint32_t pack2(__nv_bfloat16 a, __nv_bfloat16 b) {
    __nv_bfloat162 p; p.x = a; p.y = b;
    return *(uint32_t*)&p;
}
__device__ __forceinline__ uint2 split4(float4 v, uint2& lo) {
    __nv_bfloat16 h0, l0, h1, l1, h2, l2, h3, l3;
    bsplit(v.x, h0, l0); bsplit(v.y, h1, l1);
    bsplit(v.z, h2, l2); bsplit(v.w, h3, l3);
    lo = make_uint2(pack2(l0, l1), pack2(l2, l3));
    return make_uint2(pack2(h0, h1), pack2(h2, h3));
}
__device__ __forceinline__ void cp16(uint32_t dst, const void* src, int valid) {
    asm volatile("cp.async.cg.shared.global [%0], [%1], 16, %2;"
                 :: "r"(dst), "l"(src), "r"(valid ? 16 : 0) : "memory");
}
template <int N> __device__ __forceinline__ void cpwait() {
    asm volatile("cp.async.wait_group %0;" :: "n"(N) : "memory");
}
__device__ __forceinline__ void cpcommit() {
    asm volatile("cp.async.commit_group;" ::: "memory");
}
__device__ __forceinline__ void mma16816(float* c, const uint32_t* a, uint32_t b0, uint32_t b1) {
    asm volatile("mma.sync.aligned.m16n8k16.row.col.f32.bf16.bf16.f32 "
        "{%0,%1,%2,%3}, {%4,%5,%6,%7}, {%8,%9}, {%0,%1,%2,%3};"
        : "+f"(c[0]), "+f"(c[1]), "+f"(c[2]), "+f"(c[3])
        : "r"(a[0]), "r"(a[1]), "r"(a[2]), "r"(a[3]), "r"(b0), "r"(b1));
}
__device__ __forceinline__ void ldmx4(uint32_t* r, uint32_t addr) {
    asm volatile("ldmatrix.sync.aligned.m8n8.x4.shared.b16 {%0,%1,%2,%3}, [%4];"
        : "=r"(r[0]), "=r"(r[1]), "=r"(r[2]), "=r"(r[3]) : "r"(addr));
}
__device__ __forceinline__ void ldmx4t(uint32_t* r, uint32_t addr) {
    asm volatile("ldmatrix.sync.aligned.m8n8.x4.trans.shared.b16 {%0,%1,%2,%3}, [%4];"
        : "=r"(r[0]), "=r"(r[1]), "=r"(r[2]), "=r"(r[3]) : "r"(addr));
}

// ---------------- tensor-core GEMM (mma.sync + ldmatrix, bf16 3-term split) ----------------
#define KC 32
#define SROW 40
#define BROWB 272
#define A_L_OFF 10240
#define B_H_OFF 20480
#define B_L_OFF 29184
#define STAGE_BYTES 37888
#define GEMM_SMEM_BYTES (2 * STAGE_BYTES)   // 75776
#define ZT_BYTES 10240
#define W1_OFF 40960

__global__ void __launch_bounds__(256, 2)
gemm_tc(const __nv_bfloat16* __restrict__ Ah, const __nv_bfloat16* __restrict__ Al,
        const __nv_bfloat16* __restrict__ Bh_g, const __nv_bfloat16* __restrict__ Bl_g,
        const float* __restrict__ bias,
        float* __restrict__ Cf, __nv_bfloat16* __restrict__ Ch, __nv_bfloat16* __restrict__ Cl,
        int ldc, int M, int K, int relu,
        long aS, long bS, long biasS, long cS,
        int Msplit, int attn_fuse,
        const __nv_bfloat16* __restrict__ w1h, const float* __restrict__ b1a,
        const float* __restrict__ w2, float* __restrict__ s_out,
        int dual,
        const __nv_bfloat16* Ah2, const __nv_bfloat16* Al2,
        const __nv_bfloat16* Bh2, const __nv_bfloat16* Bl2,
        const float* bias2, __nv_bfloat16* Ch2, __nv_bfloat16* Cl2,
        int K2, long aS2) {
    extern __shared__ __align__(16) char sm[];
    __shared__ float bias_s[128];
    __shared__ float b1_s[128];
    __shared__ float w2_s[128];
    __shared__ float red_s[8];
    uint32_t sb = smem_u32(sm);
    int t = threadIdx.x;
    int lane = t & 31, wid = t >> 5;
    int m0 = blockIdx.x * 128;
    int rrel = blockIdx.y;
    if (dual && rrel >= CR) {
        rrel -= CR;
        Ah = Ah2; Al = Al2; Bh_g = Bh2; Bl_g = Bl2; bias = bias2;
        Ch = Ch2; Cl = Cl2; K = K2; aS = aS2;
        Bh_g += (size_t)rrel * (256L * 128); Bl_g += (size_t)rrel * (256L * 128);
        bias += (size_t)rrel * 128;
        Ch += (size_t)rrel * cS; Cl += (size_t)rrel * cS;
        Ah += (size_t)rrel * aS; Al += (size_t)rrel * aS;
    } else {
        Ah += (size_t)rrel * aS;  Al += (size_t)rrel * aS;
        Bh_g += (size_t)rrel * bS; Bl_g += (size_t)rrel * bS;
        bias += (size_t)rrel * biasS;
        if (Cf) Cf += (size_t)rrel * cS;
        if (Ch) { Ch += (size_t)rrel * cS; Cl += (size_t)rrel * cS; }
    }
    if (t < 128) {
        bias_s[t] = bias[t];
        if (attn_fuse) { b1_s[t] = b1a[t]; w2_s[t] = w2[t]; }
    }

    float acc[2][8][4];
#pragma unroll
    for (int i = 0; i < 2; i++)
#pragma unroll
        for (int j = 0; j < 8; j++)
#pragma unroll
            for (int q = 0; q < 4; q++) acc[i][j][q] = 0.f;

    const int nC = K >> 5;
    const int wm = (wid >> 1) * 32, wn = (wid & 1) * 64;
    const int t4 = lane >> 2, q2 = (lane & 3) * 2;
    const int g = lane >> 3, lr = lane & 7;

    auto load_stage = [&](int st, int c) {
        uint32_t base = sb + st * STAGE_BYTES;
        int kb = c * KC;
#pragma unroll
        for (int h = 0; h < 2; h++) {
            int idx = t + h * 256;
            int arow = idx >> 2, aseg = idx & 3;
            uint32_t aoff = (uint32_t)(arow * (SROW * 2) + aseg * 16);
            int av = (m0 + arow) < M;
            size_t asrc = (size_t)(av ? (m0 + arow) : 0) * K + kb + aseg * 8;
            cp16(base + aoff,           Ah + asrc, av);
            cp16(base + A_L_OFF + aoff, Al + asrc, av);
            int brow = idx >> 4, bseg = idx & 15;
            uint32_t boff = (uint32_t)(brow * BROWB + bseg * 16);
            size_t bsrc = (size_t)(kb + brow) * 128 + bseg * 8;
            cp16(base + B_H_OFF + boff, Bh_g + bsrc, 1);
            cp16(base + B_L_OFF + boff, Bl_g + bsrc, 1);
        }
        cpcommit();
    };

    auto compute_stage = [&](int st) {
        uint32_t base = sb + st * STAGE_BYTES;
#pragma unroll
        for (int k16 = 0; k16 < 2; k16++) {
            int k0 = k16 * 16;
            int arow = wm + (g & 1) * 8 + lr;
            int acol = k0 + (g >> 1) * 8;
            uint32_t ah[2][4], al[2][4];
#pragma unroll
            for (int i = 0; i < 2; i++) {
                uint32_t aoff = (uint32_t)(((arow + i * 16) * SROW + acol) * 2);
                ldmx4(ah[i], base + aoff);
                ldmx4(al[i], base + A_L_OFF + aoff);
            }
#pragma unroll
            for (int jp = 0; jp < 4; jp++) {
                int n0 = wn + jp * 16;
                uint32_t boff = (uint32_t)((k0 + (g & 1) * 8 + lr) * BROWB
                                           + (n0 + (g >> 1) * 8) * 2);
                uint32_t bh[4], bl[4];
                ldmx4t(bh, base + B_H_OFF + boff);
                ldmx4t(bl, base + B_L_OFF + boff);
#pragma unroll
                for (int jj = 0; jj < 2; jj++) {
                    int j = jp * 2 + jj;
#pragma unroll
                    for (int i = 0; i < 2; i++) {
                        mma16816(acc[i][j], ah[i], bh[jj * 2], bh[jj * 2 + 1]);
                        mma16816(acc[i][j], ah[i], bl[jj * 2], bl[jj * 2 + 1]);
                        mma16816(acc[i][j], al[i], bh[jj * 2], bh[jj * 2 + 1]);
                    }
                }
            }
        }
    };

    load_stage(0, 0);
    for (int c = 0; c < nC; c++) {
        if (c + 1 < nC) {
            load_stage((c + 1) & 1, c + 1);
            cpwait<1>();
        } else {
            cpwait<0>();
        }
        __syncthreads();
        compute_stage(c & 1);
        __syncthreads();
    }

    if (attn_fuse) {
#pragma unroll
        for (int i = 0; i < 2; i++) {
            int rl = wm + i * 16 + t4;
            int r0 = m0 + rl;
#pragma unroll
            for (int j = 0; j < 8; j++) {
                int col = wn + j * 8 + q2;
                float v00 = acc[i][j][0] + bias_s[col];
                float v01 = acc[i][j][1] + bias_s[col + 1];
                float v10 = acc[i][j][2] + bias_s[col];
                float v11 = acc[i][j][3] + bias_s[col + 1];
                if (r0 < M) *(float2*)(Cf + (size_t)r0 * ldc + col) = make_float2(v00, v01);
                if (r0 + 8 < M) *(float2*)(Cf + (size_t)(r0 + 8) * ldc + col) = make_float2(v10, v11);
                uint32_t zoff = (uint32_t)(col >> 5) * ZT_BYTES;
                uint32_t cw = (uint32_t)(col & 31);
                *(uint32_t*)(sm + zoff + (rl * SROW + cw) * 2) =
                    pack2(__float2bfloat16(v00), __float2bfloat16(v01));
                *(uint32_t*)(sm + zoff + ((rl + 8) * SROW + cw) * 2) =
                    pack2(__float2bfloat16(v10), __float2bfloat16(v11));
            }
        }
        __syncthreads();
        float tacc[2][8][4];
#pragma unroll
        for (int i = 0; i < 2; i++)
#pragma unroll
            for (int j = 0; j < 8; j++)
#pragma unroll
                for (int q = 0; q < 4; q++) tacc[i][j][q] = 0.f;
        for (int c = 0; c < 4; c++) {
#pragma unroll
            for (int h = 0; h < 2; h++) {
                int idx = t + h * 256;
                int brow = idx >> 4, bseg = idx & 15;
                cp16(sb + W1_OFF + (uint32_t)(brow * BROWB + bseg * 16),
                     w1h + (size_t)(c * 32 + brow) * 128 + bseg * 8, 1);
            }
            cpcommit();
            cpwait<0>();
            __syncthreads();
            uint32_t zb = sb + (uint32_t)c * ZT_BYTES;
#pragma unroll
            for (int k16 = 0; k16 < 2; k16++) {
                int k0 = k16 * 16;
                int arow = wm + (g & 1) * 8 + lr;
                int acol = k0 + (g >> 1) * 8;
                uint32_t ah[2][4];
#pragma unroll
                for (int i = 0; i < 2; i++)
                    ldmx4(ah[i], zb + (uint32_t)(((arow + i * 16) * SROW + acol) * 2));
#pragma unroll
                for (int jp = 0; jp < 4; jp++) {
                    int n0 = wn + jp * 16;
                    uint32_t bh[4];
                    ldmx4t(bh, sb + W1_OFF +
                           (uint32_t)((k0 + (g & 1) * 8 + lr) * BROWB + (n0 + (g >> 1) * 8) * 2));
#pragma unroll
                    for (int jj = 0; jj < 2; jj++)
#pragma unroll
                        for (int i = 0; i < 2; i++)
                            mma16816(tacc[i][jp * 2 + jj], ah[i], bh[jj * 2], bh[jj * 2 + 1]);
                }
            }
            __syncthreads();
        }
        float part = 0.f;
#pragma unroll
        for (int i = 0; i < 2; i++) {
            int r0 = m0 + wm + i * 16 + t4;
#pragma unroll
            for (int j = 0; j < 8; j++) {
                int col = wn + j * 8 + q2;
                float b0v = b1_s[col], b1v = b1_s[col + 1];
                float w0v = w2_s[col], w1v = w2_s[col + 1];
                if (r0 < M) {
                    part += tanhf(tacc[i][j][0] + b0v) * w0v;
                    part += tanhf(tacc[i][j][1] + b1v) * w1v;
                }
                if (r0 + 8 < M) {
                    part += tanhf(tacc[i][j][2] + b0v) * w0v;
                    part += tanhf(tacc[i][j][3] + b1v) * w1v;
                }
            }
        }
        for (int o = 16; o; o >>= 1) part += __shfl_xor_sync(0xffffffffu, part, o);
        if (lane == 0) red_s[wid] = part;
        __syncthreads();
        if (t == 0) {
            float tot = 0.f;
#pragma unroll
            for (int i = 0; i < 8; i++) tot += red_s[i];
            atomicAdd(s_out + rrel, tot);
        }
        return;
    }

#pragma unroll
    for (int i = 0; i < 2; i++) {
        int r0 = m0 + wm + i * 16 + t4;
#pragma unroll
        for (int j = 0; j < 8; j++) {
            int col = wn + j * 8 + q2;
            float b0v = bias_s[col], b1v = bias_s[col + 1];
            float v00 = acc[i][j][0] + b0v, v01 = acc[i][j][1] + b1v;
            float v10 = acc[i][j][2] + b0v, v11 = acc[i][j][3] + b1v;
            if (relu) {
                v00 = fmaxf(v00, 0.f); v01 = fmaxf(v01, 0.f);
                v10 = fmaxf(v10, 0.f); v11 = fmaxf(v11, 0.f);
            }
            if (r0 < M) {
                if (Cf) *(float2*)(Cf + (size_t)r0 * ldc + col) = make_float2(v00, v01);
                if (Ch && r0 < Msplit) {
                    __nv_bfloat16 h0, l0, h1, l1;
                    bsplit(v00, h0, l0); bsplit(v01, h1, l1);
                    *(uint32_t*)(Ch + (size_t)r0 * ldc + col) = pack2(h0, h1);
                    *(uint32_t*)(Cl + (size_t)r0 * ldc + col) = pack2(l0, l1);
                }
            }
            if (r0 + 8 < M) {
                if (Cf) *(float2*)(Cf + (size_t)(r0 + 8) * ldc + col) = make_float2(v10, v11);
                if (Ch && r0 + 8 < Msplit) {
                    __nv_bfloat16 h0, l0, h1, l1;
                    bsplit(v10, h0, l0); bsplit(v11, h1, l1);
                    *(uint32_t*)(Ch + (size_t)(r0 + 8) * ldc + col) = pack2(h0, h1);
                    *(uint32_t*)(Cl + (size_t)(r0 + 8) * ldc + col) = pack2(l0, l1);
                }
            }
        }
    }
}

// ---------------- conversions (vectorized) ----------------
__global__ void split_k(const float* __restrict__ src, __nv_bfloat16* __restrict__ h,
                        __nv_bfloat16* __restrict__ l, long n4) {
    long i = (long)blockIdx.x * blockDim.x + threadIdx.x;
    if (i >= n4) return;
    float4 v = ((const float4*)src)[i];
    uint2 lo, hi = split4(v, lo);
    ((uint2*)h)[i] = hi;
    ((uint2*)l)[i] = lo;
}
__global__ void wsplit_k(const float* w0, const float* w1, const float* w2,
                         const float* w3, const float* w4, const float* w5,
                         const float* w6, const float* w7,
                         __nv_bfloat16* __restrict__ h, __nv_bfloat16* __restrict__ l) {
    long i4 = (long)blockIdx.x * blockDim.x + threadIdx.x;
    if (i4 >= WT_TOTAL / 4) return;
    long i = i4 * 4;
    const float* src; long base;
    if      (i < OFF_ATTN)  { src = w0; base = OFF_EMBED; }
    else if (i < OFF_L1FC1) { src = w1; base = OFF_ATTN; }
    else if (i < OFF_L1FC2) { src = w2; base = OFF_L1FC1; }
    else if (i < OFF_L1FC3) { src = w3; base = OFF_L1FC2; }
    else if (i < OFF_L2FC1) { src = w4; base = OFF_L1FC3; }
    else if (i < OFF_L2FC2) { src = w5; base = OFF_L2FC1; }
    else if (i < OFF_L2FC3) { src = w6; base = OFF_L2FC2; }
    else                    { src = w7; base = OFF_L2FC3; }
    float4 v = *(const float4*)(src + (i - base));
    uint2 lo, hi = split4(v, lo);
    *(uint2*)(h + i) = hi;
    *(uint2*)(l + i) = lo;
}

// ---------------- CSR build: BOTH layers in single launches ----------------
__global__ void hist_both_k(const int* __restrict__ d0, const int* __restrict__ d1,
                            int* cnt1, int* cnt2) {
    int e = blockIdx.x * blockDim.x + threadIdx.x;
    if (e < CR * CE0) {
        int r = e / CE0;
        atomicAdd(&cnt1[r * CN1 + d0[e]], 1);
    } else {
        int e2 = e - CR * CE0;
        if (e2 < CR * CE1) {
            int r = e2 / CE1;
            atomicAdd(&cnt2[r * CN2 + d1[e2]], 1);
        }
    }
}
// grid.x = 2*CR: blocks [0,CR) layer1 (n=CN1), [CR,2CR) layer2 (n=CN2)
__global__ void scan_both_k(int* cnt1, int* rowptr1, int* cursor1,
                            int* cnt2, int* rowptr2, int* cursor2) {
    int b = blockIdx.x;
    int n;
    int *cnt, *rowptr, *cursor;
    if (b < CR) {
        n = CN1;
        cnt = cnt1 + b * CN1; rowptr = rowptr1 + b * (CN1 + 1); cursor = cursor1 + b * (CN1 + 1);
    } else {
        int rel = b - CR;
        n = CN2;
        cnt = cnt2 + rel * CN2; rowptr = rowptr2 + rel * (CN2 + 1); cursor = cursor2 + rel * (CN2 + 1);
    }
    __shared__ int sh[1024];
    __shared__ int carry_s;
    if (threadIdx.x == 0) carry_s = 0;
    __syncthreads();
    for (int base = 0; base < n; base += 1024) {
        int i = base + threadIdx.x;
        int v = (i < n) ? cnt[i] : 0;
        sh[threadIdx.x] = v;
        __syncthreads();
        for (int off = 1; off < 1024; off <<= 1) {
            int add = (threadIdx.x >= off) ? sh[threadIdx.x - off] : 0;
            __syncthreads();
            sh[threadIdx.x] += add;
            __syncthreads();
        }
        int carry = carry_s;
        if (i < n) {
            int excl = carry + sh[threadIdx.x] - v;
            rowptr[i] = excl;
            cursor[i] = excl;
            cnt[i] = 0;    // restore zero-invariant
        }
        __syncthreads();
        if (threadIdx.x == 0) carry_s = carry + sh[1023];
        __syncthreads();
    }
    if (threadIdx.x == 0) rowptr[n] = carry_s;
}
__global__ void scatter_both_k(const int* __restrict__ s0, const int* __restrict__ d0,
                               const int* __restrict__ s1, const int* __restrict__ d1,
                               int* cursor1, int* sorted1, int* cursor2, int* sorted2) {
    int e = blockIdx.x * blockDim.x + threadIdx.x;
    if (e < CR * CE0) {
        int r = e / CE0;
        int p = atomicAdd(&cursor1[r * (CN1 + 1) + d0[e]], 1);
        sorted1[r * CE0 + p] = s0[e];
    } else {
        int e2 = e - CR * CE0;
        if (e2 < CR * CE1) {
            int r = e2 / CE1;
            int p = atomicAdd(&cursor2[r * (CN2 + 1) + d1[e2]], 1);
            sorted2[r * CE1 + p] = s1[e2];
        }
    }
}

// ---------------- segment aggregation: 32 threads/node, 8 feats, 4-edge unroll ----------------
__device__ __forceinline__ void load8(const __nv_bfloat16* fh, const __nv_bfloat16* fl,
                                      size_t off, float* v) {
    uint4 h = *(const uint4*)(fh + off);
    uint4 l = *(const uint4*)(fl + off);
    const __nv_bfloat162* hp = (const __nv_bfloat162*)&h;
    const __nv_bfloat162* lp = (const __nv_bfloat162*)&l;
#pragma unroll
    for (int k = 0; k < 4; k++) {
        float2 hf = __bfloat1622float2(hp[k]);
        float2 lf = __bfloat1622float2(lp[k]);
        v[2 * k]     = hf.x + lf.x;
        v[2 * k + 1] = hf.y + lf.y;
    }
}
__global__ void __launch_bounds__(256)
aggregate_k(const __nv_bfloat16* __restrict__ fh, const __nv_bfloat16* __restrict__ fl,
            const int* __restrict__ rowptr_g, const int* __restrict__ sorted_g,
            __nv_bfloat16* __restrict__ mh_g, __nv_bfloat16* __restrict__ ml_g,
            int N, int E) {
    int rel = blockIdx.y;
    const int* rowptr = rowptr_g + rel * (N + 1);
    const int* sorted = sorted_g + rel * E;
    __nv_bfloat16* mh = mh_g + (size_t)rel * N * 768;
    __nv_bfloat16* ml = ml_g + (size_t)rel * N * 768;
    int n = blockIdx.x * 8 + (threadIdx.x >> 5);
    if (n >= N) return;
    int f8 = (threadIdx.x & 31) * 8;
    int start = rowptr[n], end = rowptr[n + 1];
    int deg = end - start;
    float sum[8], mx[8];
#pragma unroll
    for (int k = 0; k < 8; k++) { sum[k] = 0.f; mx[k] = -3.402823e38f; }
    int e = start;
    for (; e + 3 < end; e += 4) {
        int i0 = sorted[e], i1 = sorted[e + 1], i2 = sorted[e + 2], i3 = sorted[e + 3];
        float v0[8], v1[8], v2[8], v3[8];
        load8(fh, fl, (size_t)i0 * CFEAT + f8, v0);
        load8(fh, fl, (size_t)i1 * CFEAT + f8, v1);
        load8(fh, fl, (size_t)i2 * CFEAT + f8, v2);
        load8(fh, fl, (size_t)i3 * CFEAT + f8, v3);
#pragma unroll
        for (int k = 0; k < 8; k++) {
            sum[k] += (v0[k] + v1[k]) + (v2[k] + v3[k]);
            mx[k] = fmaxf(mx[k], fmaxf(fmaxf(v0[k], v1[k]), fmaxf(v2[k], v3[k])));
        }
    }
    for (; e < end; e++) {
        int i0 = sorted[e];
        float v0[8];
        load8(fh, fl, (size_t)i0 * CFEAT + f8, v0);
#pragma unroll
        for (int k = 0; k < 8; k++) {
            sum[k] += v0[k];
            mx[k] = fmaxf(mx[k], v0[k]);
        }
    }
    if (deg == 0)
#pragma unroll
        for (int k = 0; k < 8; k++) mx[k] = 0.f;
    float inv = 1.0f / (float)max(deg, 1);
    size_t o = (size_t)n * 768 + f8;
    uint2 lo0, lo1, hi0, hi1;
    hi0 = split4(*(float4*)(mx + 0), lo0); hi1 = split4(*(float4*)(mx + 4), lo1);
    *(uint4*)(mh + o) = make_uint4(hi0.x, hi0.y, hi1.x, hi1.y);
    *(uint4*)(ml + o) = make_uint4(lo0.x, lo0.y, lo1.x, lo1.y);
    float mean[8];
#pragma unroll
    for (int k = 0; k < 8; k++) mean[k] = sum[k] * inv;
    hi0 = split4(*(float4*)(mean + 0), lo0); hi1 = split4(*(float4*)(mean + 4), lo1);
    *(uint4*)(mh + o + 256) = make_uint4(hi0.x, hi0.y, hi1.x, hi1.y);
    *(uint4*)(ml + o + 256) = make_uint4(lo0.x, lo0.y, lo1.x, lo1.y);
    hi0 = split4(*(float4*)(sum + 0), lo0); hi1 = split4(*(float4*)(sum + 4), lo1);
    *(uint4*)(mh + o + 512) = make_uint4(hi0.x, hi0.y, hi1.x, hi1.y);
    *(uint4*)(ml + o + 512) = make_uint4(lo0.x, lo0.y, lo1.x, lo1.y);
}

// ---------------- feature assembly (bf16 split only) ----------------
__global__ void __launch_bounds__(256)
fill_embed_k(const float* __restrict__ tss, const float* __restrict__ rs,
             const int* __restrict__ nid,
             __nv_bfloat16* __restrict__ f0h, __nv_bfloat16* __restrict__ f0l) {
    int n = blockIdx.x * 8 + (threadIdx.x >> 5);
    int lane = threadIdx.x & 31;
    if (n >= CN0) return;
    int id = nid[n];
    float4 v = (lane < 16)
        ? *(const float4*)&tss[(size_t)id * 64 + lane * 4]
        : *(const float4*)&rs[(size_t)id * 64 + (lane - 16) * 4];
    size_t o = (size_t)n * CFEAT + 128 + lane * 4;
    uint2 lo, hi = split4(v, lo);
    *(uint2*)(f0h + o) = hi;
    *(uint2*)(f0l + o) = lo;
}
__global__ void __launch_bounds__(256)
combine1_k(const float* __restrict__ z, const float* __restrict__ beta,
           const float* __restrict__ tss, const float* __restrict__ rs,
           const int* __restrict__ nid,
           __nv_bfloat16* __restrict__ f1h, __nv_bfloat16* __restrict__ f1l,
           int N) {
    int n = blockIdx.x * 4 + (threadIdx.x >> 6);
    if (n >= N) return;
    int c4 = (threadIdx.x & 63) * 4;
    float4 v;
    if (c4 < 128) {
        float b0 = beta[0], b1 = beta[1], b2 = beta[2];
        float4 z0 = *(const float4*)&z[(size_t)n * 128 + c4];
        float4 z1 = *(const float4*)&z[((size_t)N + n) * 128 + c4];
        float4 z2 = *(const float4*)&z[(2 * (size_t)N + n) * 128 + c4];
        v.x = fmaxf(b0 * z0.x + b1 * z1.x + b2 * z2.x, 0.f);
        v.y = fmaxf(b0 * z0.y + b1 * z1.y + b2 * z2.y, 0.f);
        v.z = fmaxf(b0 * z0.z + b1 * z1.z + b2 * z2.z, 0.f);
        v.w = fmaxf(b0 * z0.w + b1 * z1.w + b2 * z2.w, 0.f);
    } else if (c4 < 192) {
        v = *(const float4*)&tss[(size_t)nid[n] * 64 + (c4 - 128)];
    } else {
        v = *(const float4*)&rs[(size_t)nid[n] * 64 + (c4 - 192)];
    }
    size_t o = (size_t)n * CFEAT + c4;
    uint2 lo, hi = split4(v, lo);
    *(uint2*)(f1h + o) = hi;
    *(uint2*)(f1l + o) = lo;
}

__global__ void beta_k(float* __restrict__ s, float* beta, float invN) {
    if (threadIdx.x == 0) {
        float w0 = s[0] * invN, w1 = s[1] * invN, w2 = s[2] * invN;
        s[0] = 0.f; s[1] = 0.f; s[2] = 0.f;
        float m = fmaxf(w0, fmaxf(w1, w2));
        float e0 = expf(w0 - m), e1 = expf(w1 - m), e2 = expf(w2 - m);
        float d = e0 + e1 + e2;
        beta[0] = e0 / d; beta[1] = e1 / d; beta[2] = e2 / d;
    }
}
__global__ void final_k(const float* __restrict__ z, const float* __restrict__ beta,
                        const float* __restrict__ pred_w, const float* __restrict__ pred_b,
                        float* __restrict__ out, int N) {
    int n = blockIdx.x * 8 + (threadIdx.x >> 5);
    int lane = threadIdx.x & 31;
    if (n >= N) return;
    float b0 = beta[0], b1 = beta[1], b2 = beta[2];
    int c4 = lane * 4;
    float4 z0 = *(const float4*)&z[(size_t)n * 128 + c4];
    float4 z1 = *(const float4*)&z[((size_t)N + n) * 128 + c4];
    float4 z2 = *(const float4*)&z[(2 * (size_t)N + n) * 128 + c4];
    float4 w = *(const float4*)&pred_w[c4];
    float acc = (b0 * z0.x + b1 * z1.x + b2 * z2.x) * w.x
              + (b0 * z0.y + b1 * z1.y + b2 * z2.y) * w.y
              + (b0 * z0.z + b1 * z1.z + b2 * z2.z) * w.z
              + (b0 * z0.w + b1 * z1.w + b2 * z2.w) * w.w;
    for (int o = 16; o; o >>= 1) acc += __shfl_xor_sync(0xffffffffu, acc, o);
    if (lane == 0) out[n] = 1.f / (1.f + expf(-(acc + pred_b[0])));
}

// ---------------- host orchestration (single stream) ----------------
static inline void launch_gemm(int R, const __nv_bfloat16* Ah, const __nv_bfloat16* Al,
                               const __nv_bfloat16* Bh, const __nv_bfloat16* Bl,
                               const float* bias, float* Cf, __nv_bfloat16* Ch,
                               __nv_bfloat16* Cl, int ldc, int M, int K, int relu,
                               long aS, long bS, long biasS, long cS,
                               int Msplit, int attn_fuse = 0,
                               const __nv_bfloat16* w1h = nullptr,
                               const float* b1a = nullptr,
                               const float* w2 = nullptr, float* s_out = nullptr,
                               int dual = 0,
                               const __nv_bfloat16* Ah2 = nullptr,
                               const __nv_bfloat16* Al2 = nullptr,
                               const __nv_bfloat16* Bh2 = nullptr,
                               const __nv_bfloat16* Bl2 = nullptr,
                               const float* bias2 = nullptr,
                               __nv_bfloat16* Ch2 = nullptr, __nv_bfloat16* Cl2 = nullptr,
                               int K2 = 0, long aS2 = 0) {
    dim3 grid((M + 127) / 128, dual ? 2 * R : R);
    gemm_tc<<<grid, 256, GEMM_SMEM_BYTES>>>(Ah, Al, Bh, Bl, bias, Cf, Ch, Cl,
                                            ldc, M, K, relu, aS, bS, biasS, cS,
                                            Msplit, attn_fuse, w1h, b1a, w2, s_out,
                                            dual, Ah2, Al2, Bh2, Bl2, bias2, Ch2, Cl2,
                                            K2, aS2);
}

extern "C" void kernel_launch(void* const* d_in, const int* in_sizes, int n_in,
                              void* d_out, int out_size) {
    const float* x_user   = (const float*)d_in[0];
    const float* tss      = (const float*)d_in[1];
    const float* rs       = (const float*)d_in[2];
    const int*   src_nid0 = (const int*)d_in[3];
    const int*   src_nid1 = (const int*)d_in[4];
    const int*   e0_src   = (const int*)d_in[5];
    const int*   e0_dst   = (const int*)d_in[6];
    const int*   e1_src   = (const int*)d_in[7];
    const int*   e1_dst   = (const int*)d_in[8];
    const float* embed_w  = (const float*)d_in[9];
    const float* embed_b  = (const float*)d_in[10];
    const float* l1_fc1_w = (const float*)d_in[11];
    const float* l1_fc1_b = (const float*)d_in[12];
    const float* l1_fc2_w = (const float*)d_in[13];
    const float* l1_fc2_b = (const float*)d_in[14];
    const float* l1_fc3_w = (const float*)d_in[15];
    const float* l1_fc3_b = (const float*)d_in[16];
    const float* l2_fc1_w = (const float*)d_in[17];
    const float* l2_fc1_b = (const float*)d_in[18];
    const float* l2_fc2_w = (const float*)d_in[19];
    const float* l2_fc2_b = (const float*)d_in[20];
    const float* l2_fc3_w = (const float*)d_in[21];
    const float* l2_fc3_b = (const float*)d_in[22];
    const float* attn_w1  = (const float*)d_in[23];
    const float* attn_b1  = (const float*)d_in[24];
    const float* attn_w2  = (const float*)d_in[25];
    const float* pred_w   = (const float*)d_in[26];
    const float* pred_b   = (const float*)d_in[27];
    float* out = (float*)d_out;

    cudaFuncSetAttribute(gemm_tc, cudaFuncAttributeMaxDynamicSharedMemorySize, GEMM_SMEM_BYTES);

    float *z, *s, *beta;
    __nv_bfloat16 *xh, *xl, *f0h, *f0l, *f1h, *f1l, *msgh, *msgl, *Hh, *Hl, *wth, *wtl;
    int *cnt, *rowptr, *cursor, *sorted;
    int *cnt2, *rowptr2, *cursor2, *sorted2;
    cudaGetSymbolAddress((void**)&z, g_z);
    cudaGetSymbolAddress((void**)&s, g_s);
    cudaGetSymbolAddress((void**)&beta, g_beta);
    cudaGetSymbolAddress((void**)&xh, g_xh);
    cudaGetSymbolAddress((void**)&xl, g_xl);
    cudaGetSymbolAddress((void**)&f0h, g_f0h);
    cudaGetSymbolAddress((void**)&f0l, g_f0l);
    cudaGetSymbolAddress((void**)&f1h, g_f1h);
    cudaGetSymbolAddress((void**)&f1l, g_f1l);
    cudaGetSymbolAddress((void**)&msgh, g_msgh);
    cudaGetSymbolAddress((void**)&msgl, g_msgl);
    cudaGetSymbolAddress((void**)&Hh, g_Hh);
    cudaGetSymbolAddress((void**)&Hl, g_Hl);
    cudaGetSymbolAddress((void**)&wth, g_wth);
    cudaGetSymbolAddress((void**)&wtl, g_wtl);
    cudaGetSymbolAddress((void**)&cnt, g_cnt);
    cudaGetSymbolAddress((void**)&rowptr, g_rowptr);
    cudaGetSymbolAddress((void**)&cursor, g_cursor);
    cudaGetSymbolAddress((void**)&sorted, g_sorted);
    cudaGetSymbolAddress((void**)&cnt2, g_cnt2);
    cudaGetSymbolAddress((void**)&rowptr2, g_rowptr2);
    cudaGetSymbolAddress((void**)&cursor2, g_cursor2);
    cudaGetSymbolAddress((void**)&sorted2, g_sorted2);

    // ---- conversions ----
    wsplit_k<<<(WT_TOTAL / 4 + 255) / 256, 256>>>(embed_w, attn_w1, l1_fc1_w, l1_fc2_w,
                                                  l1_fc3_w, l2_fc1_w, l2_fc2_w, l2_fc3_w,
                                                  wth, wtl);
    split_k<<<((long)CN0 * 32 + 255) / 256, 256>>>(x_user, xh, xl, (long)CN0 * 32);

    // ---- CSR for BOTH layers (merged launches) ----
    int histN = CR * CE0 + CR * CE1;
    hist_both_k<<<(histN + 255) / 256, 256>>>(e0_dst, e1_dst, cnt, cnt2);
    scan_both_k<<<2 * CR, 1024>>>(cnt, rowptr, cursor, cnt2, rowptr2, cursor2);
    scatter_both_k<<<(histN + 255) / 256, 256>>>(e0_src, e0_dst, e1_src, e1_dst,
                                                 cursor, sorted, cursor2, sorted2);

    // feat0 split = [x_user@embed_w + b | tss | rs]
    launch_gemm(1, xh, xl, wth + OFF_EMBED, wtl + OFF_EMBED, embed_b,
                nullptr, f0h, f0l, CFEAT, CN0, 128, 0, 0, 0, 0, 0, CN0);
    fill_embed_k<<<(CN0 + 7) / 8, 256>>>(tss, rs, src_nid0, f0h, f0l);

    // ---- layer 1 ----
    aggregate_k<<<dim3((CN1 + 7) / 8, CR), 256>>>(f0h, f0l, rowptr, sorted, msgh, msgl, CN1, CE0);
    launch_gemm(CR, msgh, msgl, wth + OFF_L1FC2, wtl + OFF_L1FC2, l1_fc2_b,
                nullptr, Hh, Hl, 256, CN1, 768, 1,
                (long)CN1 * 768, 768L * 128, 128, (long)CN1 * 256, CN1,
                0, nullptr, nullptr, nullptr, nullptr,
                1, f0h, f0l, wth + OFF_L1FC1, wtl + OFF_L1FC1, l1_fc1_b,
                Hh + 128, Hl + 128, 256, 0);
    launch_gemm(CR, Hh, Hl, wth + OFF_L1FC3, wtl + OFF_L1FC3, l1_fc3_b,
                z, nullptr, nullptr, 128, CN1, 256, 0,
                (long)CN1 * 256, 256L * 128, 128, (long)CN1 * 128, 0,
                1, wth + OFF_ATTN, attn_b1, attn_w2, s);
    beta_k<<<1, 32>>>(s, beta, 1.0f / (float)CN1);
    combine1_k<<<(CN1 + 3) / 4, 256>>>(z, beta, tss, rs, src_nid1, f1h, f1l, CN1);

    // ---- layer 2 ----
    aggregate_k<<<dim3((CN2 + 7) / 8, CR), 256>>>(f1h, f1l, rowptr2, sorted2, msgh, msgl, CN2, CE1);
    launch_gemm(CR, msgh, msgl, wth + OFF_L2FC2, wtl + OFF_L2FC2, l2_fc2_b,
                nullptr, Hh, Hl, 256, CN2, 768, 1,
                (long)CN2 * 768, 768L * 128, 128, (long)CN2 * 256, CN2,
                0, nullptr, nullptr, nullptr, nullptr,
                1, f1h, f1l, wth + OFF_L2FC1, wtl + OFF_L2FC1, l2_fc1_b,
                Hh + 128, Hl + 128, 256, 0);
    launch_gemm(CR, Hh, Hl, wth + OFF_L2FC3, wtl + OFF_L2FC3, l2_fc3_b,
                z, nullptr, nullptr, 128, CN2, 256, 0,
                (long)CN2 * 256, 256L * 128, 128, (long)CN2 * 128, 0,
                1, wth + OFF_ATTN, attn_b1, attn_w2, s);
    beta_k<<<1, 32>>>(s, beta, 1.0f / (float)CN2);
    final_k<<<(CN2 + 7) / 8, 256>>>(z, beta, pred_w, pred_b, out, CN2);
}